// round 11
// baseline (speedup 1.0000x reference)
#include <cuda_runtime.h>

// Problem constants: x [2, 64, 64, 96, 96]; NSEQ = bs*c = 128; T = d = 64; HID = 4
#define NSEQ 128
#define TSTEPS 64
#define ROWVEC 2304          // 96*96/4
#define VECS_PER_BC 147456   // 64*96*96/4
#define NLSTMBLK 32

__device__ float g_mean[NSEQ * TSTEPS];            // [seq=b*64+c][t=d]
__device__ __align__(16) float g_last[NSEQ * 8];   // [seq][fwd h(4) | bwd h(4)]
__device__ float g_scale[NSEQ];                    // sigmoid output per (b,c)
__device__ unsigned g_ctr;                         // last-lstm-block counter
__device__ unsigned seq_done[NSEQ];                // per-seq mean-row arrivals

__device__ __forceinline__ float tanh_ap(float x) {
    float y;
    asm("tanh.approx.f32 %0, %1;" : "=f"(y) : "f"(x));
    return y;
}
__device__ __forceinline__ float sig_ap(float x) {
    return fmaf(0.5f, tanh_ap(0.5f * x), 0.5f);
}
__device__ __forceinline__ float sig_acc(float x) {
    return __fdividef(1.f, 1.f + __expf(-x));
}

// ---------------------------------------------------------------------------
// Fused kernel: blocks 0..31 run the biLSTM (+ fc in the last of them),
// spinning on per-sequence counters; blocks 32..8223 compute spatial means.
// __launch_bounds__(256, 6) caps regs at ~42 so the MEAN role keeps enough
// occupancy (48 warps/SM) to saturate HBM; the lstm role's weight arrays may
// spill (static LDL, latency-tolerant, hidden under the mean phase).
// ---------------------------------------------------------------------------
__global__ __launch_bounds__(256, 6) void fused_mean_lstm_kernel(
    const float* __restrict__ x,
    const float* __restrict__ wih0f, const float* __restrict__ whh0f,
    const float* __restrict__ bih0f, const float* __restrict__ bhh0f,
    const float* __restrict__ wih0b, const float* __restrict__ whh0b,
    const float* __restrict__ bih0b, const float* __restrict__ bhh0b,
    const float* __restrict__ wih1f, const float* __restrict__ whh1f,
    const float* __restrict__ bih1f, const float* __restrict__ bhh1f,
    const float* __restrict__ wih1b, const float* __restrict__ whh1b,
    const float* __restrict__ bih1b, const float* __restrict__ bhh1b,
    const float* __restrict__ w1,    const float* __restrict__ w2) {

    if (blockIdx.x >= NLSTMBLK) {
        // ================== mean role: one block per (b,c,d) row ============
        int r = blockIdx.x - NLSTMBLK;
        const float4* p = reinterpret_cast<const float4*>(x) + (size_t)r * ROWVEC;
        float4 v[9];
#pragma unroll
        for (int i = 0; i < 9; ++i) v[i] = p[threadIdx.x + i * 256];
        float s = 0.f;
#pragma unroll
        for (int i = 0; i < 9; ++i) s += (v[i].x + v[i].y) + (v[i].z + v[i].w);
#pragma unroll
        for (int off = 16; off > 0; off >>= 1)
            s += __shfl_down_sync(0xffffffffu, s, off);
        __shared__ float red[8];
        int warp = threadIdx.x >> 5, lane = threadIdx.x & 31;
        if (lane == 0) red[warp] = s;
        __syncthreads();
        if (threadIdx.x < 8) {
            s = red[threadIdx.x];
            s += __shfl_down_sync(0xffu, s, 4);
            s += __shfl_down_sync(0xffu, s, 2);
            s += __shfl_down_sync(0xffu, s, 1);
            if (threadIdx.x == 0) {
                g_mean[r] = s * (1.f / 9216.f);
                __threadfence();
                atomicAdd(&seq_done[r >> 6], 1u);   // release this row
            }
        }
        return;
    }

    // ===================== lstm role: blocks 0..31 ==========================
    int tid = threadIdx.x;
    if (tid >= 32) return;   // single warp per lstm block
    int bid = blockIdx.x;

    __shared__ float s_mean[256];                     // 4 seqs x 64 t
    __shared__ __align__(16) float s_h0[4][516];      // 4 x (64 t x 8) + pad

    int j   = tid & 3;        // cell index within hidden=4
    int u   = tid >> 2;       // unit 0..7
    int sl  = u >> 1;         // local seq 0..3
    int dir = u & 1;

    // ---- register-load weights BEFORE the spin (overlaps the wait) ----
    const float* WIH0 = dir ? wih0b : wih0f;
    const float* WHH0 = dir ? whh0b : whh0f;
    const float* BI0  = dir ? bih0b : bih0f;
    const float* BH0  = dir ? bhh0b : bhh0f;
    float w_ih0[4], w_hh0[16], b0[4];
#pragma unroll
    for (int g = 0; g < 4; ++g) {
        int k = g * 4 + j;
        w_ih0[g] = WIH0[k];
        b0[g]    = BI0[k] + BH0[k];
#pragma unroll
        for (int m = 0; m < 4; ++m) w_hh0[g * 4 + m] = WHH0[k * 4 + m];
    }
    const float* WIH1 = (tid < 16) ? wih1f : wih1b;
    const float* WHH1 = (tid < 16) ? whh1f : whh1b;
    const float* BI1  = (tid < 16) ? bih1f : bih1b;
    const float* BH1  = (tid < 16) ? bhh1f : bhh1b;
    int j1 = tid & 3;
    float w1i[32], w1h[16], b1[4];
#pragma unroll
    for (int g = 0; g < 4; ++g) {
        int k = g * 4 + j1;
        b1[g] = BI1[k] + BH1[k];
#pragma unroll
        for (int m = 0; m < 8; ++m) w1i[g * 8 + m] = WIH1[k * 8 + m];
#pragma unroll
        for (int m = 0; m < 4; ++m) w1h[g * 4 + m] = WHH1[k * 4 + m];
    }

    // ---- wait for this block's 4 sequences (lanes 0..3 each watch one) ----
    {
        volatile unsigned* sd = (volatile unsigned*)seq_done;
        if (tid < 4) {
            while (sd[bid * 4 + tid] < 64u) __nanosleep(64);
        }
        __syncwarp();
        __threadfence();  // acquire g_mean stores
    }

#pragma unroll
    for (int i = 0; i < 8; ++i)
        s_mean[tid + i * 32] = g_mean[bid * 256 + tid + i * 32];
    __syncwarp();
    // reset counters for graph replay (sole consumer; producers all arrived)
    if (tid < 4) seq_done[bid * 4 + tid] = 0u;

    // ---------------- layer 0 ----------------
    {
        float hj = 0.f, cj = 0.f;
        const float* mrow = s_mean + sl * 64;
        float* hrow = s_h0[sl];
        int foff = dir * 4 + j;
        for (int st = 0; st < TSTEPS; ++st) {
            int t = dir ? (TSTEPS - 1 - st) : st;
            float xt = mrow[t];
            float h0 = __shfl_sync(0xffffffffu, hj, 0, 4);
            float h1 = __shfl_sync(0xffffffffu, hj, 1, 4);
            float h2 = __shfl_sync(0xffffffffu, hj, 2, 4);
            float h3 = __shfl_sync(0xffffffffu, hj, 3, 4);
            float ga[4];
#pragma unroll
            for (int g = 0; g < 4; ++g) {
                float p0 = fmaf(w_ih0[g], xt, b0[g]);
                p0 = fmaf(w_hh0[g * 4 + 0], h0, p0);
                float p1 = fmaf(w_hh0[g * 4 + 2], h2, w_hh0[g * 4 + 1] * h1);
                float p2 = w_hh0[g * 4 + 3] * h3;
                ga[g] = p0 + (p1 + p2);
            }
            float ig = sig_ap(ga[0]), fg = sig_ap(ga[1]);
            float gg = tanh_ap(ga[2]), og = sig_ap(ga[3]);
            cj = fmaf(fg, cj, ig * gg);
            hj = og * tanh_ap(cj);
            hrow[t * 8 + foff] = hj;
        }
    }
    __syncwarp();

    // ---------------- layer 1 ----------------
    if (tid < 16) {
        int s1 = tid >> 2;
        const float* hrow = s_h0[s1];
        float hj = 0.f, cj = 0.f;
        for (int t = 0; t < TSTEPS; ++t) {
            float4 xa = *reinterpret_cast<const float4*>(hrow + t * 8);
            float4 xb = *reinterpret_cast<const float4*>(hrow + t * 8 + 4);
            float h0 = __shfl_sync(0x0000ffffu, hj, 0, 4);
            float h1 = __shfl_sync(0x0000ffffu, hj, 1, 4);
            float h2 = __shfl_sync(0x0000ffffu, hj, 2, 4);
            float h3 = __shfl_sync(0x0000ffffu, hj, 3, 4);
            float ga[4];
#pragma unroll
            for (int g = 0; g < 4; ++g) {
                const float* wi = w1i + g * 8;
                const float* wh = w1h + g * 4;
                float p0 = fmaf(wi[0], xa.x, b1[g]);
                p0 = fmaf(wi[1], xa.y, p0);
                float p1 = fmaf(wi[3], xa.w, wi[2] * xa.z);
                float p2 = fmaf(wi[5], xb.y, wi[4] * xb.x);
                float p3 = fmaf(wi[7], xb.w, wi[6] * xb.z);
                float p4 = fmaf(wh[1], h1, wh[0] * h0);
                float p5 = fmaf(wh[3], h3, wh[2] * h2);
                ga[g] = ((p0 + p1) + (p2 + p3)) + (p4 + p5);
            }
            float ig = sig_ap(ga[0]), fg = sig_ap(ga[1]);
            float gg = tanh_ap(ga[2]), og = sig_ap(ga[3]);
            cj = fmaf(fg, cj, ig * gg);
            hj = og * tanh_ap(cj);
        }
        g_last[(bid * 4 + s1) * 8 + j1] = hj;
    } else {
        // backward: only the first processed step (original t = T-1) is used.
        int s1 = (tid - 16) >> 2;
        const float* hrow = s_h0[s1];
        float4 xa = *reinterpret_cast<const float4*>(hrow + (TSTEPS - 1) * 8);
        float4 xb = *reinterpret_cast<const float4*>(hrow + (TSTEPS - 1) * 8 + 4);
        float ga[4];
#pragma unroll
        for (int g = 0; g < 4; ++g) {
            const float* wi = w1i + g * 8;
            float p0 = fmaf(wi[0], xa.x, b1[g]);
            p0 = fmaf(wi[1], xa.y, p0);
            float p1 = fmaf(wi[3], xa.w, wi[2] * xa.z);
            float p2 = fmaf(wi[5], xb.y, wi[4] * xb.x);
            float p3 = fmaf(wi[7], xb.w, wi[6] * xb.z);
            ga[g] = (p0 + p1) + (p2 + p3);
        }
        float cj = sig_ap(ga[0]) * tanh_ap(ga[2]);
        float hj = sig_ap(ga[3]) * tanh_ap(cj);
        g_last[(bid * 4 + s1) * 8 + 4 + j1] = hj;
    }

    // ---------------- fc (SE MLP) in the last-arriving lstm block -----------
    __syncwarp();
    __shared__ unsigned s_last;
    if (tid == 0) {
        __threadfence();
        s_last = (atomicAdd(&g_ctr, 1u) == NLSTMBLK - 1u);
    }
    __syncwarp();
    if (!s_last) return;
    __threadfence();  // acquire: make other blocks' g_last stores visible

    __shared__ __align__(16) float z[1024];   // [b=0 512 | b=1 512]
    __shared__ float h1s[64];                 // [b=0 32 | b=1 32]
    __shared__ float w2s[2048];               // w2 staged coalesced (64 x 32)

    {
        float4* z4 = reinterpret_cast<float4*>(z);
        const float4* gl4 = reinterpret_cast<const float4*>(g_last);
#pragma unroll
        for (int i = 0; i < 8; ++i) z4[tid + i * 32] = gl4[tid + i * 32];
#pragma unroll
        for (int i = 0; i < 64; ++i) w2s[tid + i * 32] = w2[tid + i * 32];
    }
    __syncwarp();

    // h1 = relu(z @ w1.T): cooperative coalesced GEMV, 2 rows at a time.
    for (int e = 0; e < 32; e += 2) {
        const float* wr0 = w1 + e * 512;
        const float* wr1 = wr0 + 512;
        float a00 = 0.f, a01 = 0.f, a10 = 0.f, a11 = 0.f;
#pragma unroll
        for (int i = 0; i < 16; ++i) {
            int k = tid + i * 32;
            float w0 = wr0[k], w1v = wr1[k];
            float zz0 = z[k], zz1 = z[512 + k];
            a00 = fmaf(w0, zz0, a00);
            a01 = fmaf(w0, zz1, a01);
            a10 = fmaf(w1v, zz0, a10);
            a11 = fmaf(w1v, zz1, a11);
        }
#pragma unroll
        for (int off = 16; off > 0; off >>= 1) {
            a00 += __shfl_down_sync(0xffffffffu, a00, off);
            a01 += __shfl_down_sync(0xffffffffu, a01, off);
            a10 += __shfl_down_sync(0xffffffffu, a10, off);
            a11 += __shfl_down_sync(0xffffffffu, a11, off);
        }
        if (tid == 0) {
            h1s[e]          = fmaxf(a00, 0.f);
            h1s[32 + e]     = fmaxf(a01, 0.f);
            h1s[e + 1]      = fmaxf(a10, 0.f);
            h1s[32 + e + 1] = fmaxf(a11, 0.f);
        }
    }
    __syncwarp();

    // scale = sigmoid(h1 @ w2.T) from SMEM
#pragma unroll
    for (int i = 0; i < 4; ++i) {
        int idx = tid + i * 32;          // 0..127 -> (b = idx>>6, ch = idx&63)
        int b = idx >> 6, ch = idx & 63;
        const float* wr = w2s + ch * 32;
        const float* hb = h1s + b * 32;
        float acc = 0.f;
#pragma unroll
        for (int m = 0; m < 32; ++m) acc = fmaf(wr[m], hb[m], acc);
        g_scale[idx] = sig_acc(acc);
    }
    if (tid == 0) g_ctr = 0;  // reset for next graph replay
}

// ---------------------------------------------------------------------------
// Kernel 2: out = x * scale[bc]. One float4 per thread, exact grid
// (the R3-measured 86.7us configuration).
// ---------------------------------------------------------------------------
__global__ void scale_kernel(const float* __restrict__ x,
                             float* __restrict__ out) {
    unsigned v = blockIdx.x * 256u + threadIdx.x;  // < 18,874,368
    unsigned bc = v / VECS_PER_BC;                 // 0..127
    float sc = g_scale[bc];
    float4 t = reinterpret_cast<const float4*>(x)[v];
    t.x *= sc; t.y *= sc; t.z *= sc; t.w *= sc;
    __stcs(reinterpret_cast<float4*>(out) + v, t);
}

// ---------------------------------------------------------------------------
extern "C" void kernel_launch(void* const* d_in, const int* in_sizes, int n_in,
                              void* d_out, int out_size) {
    const float* x = (const float*)d_in[0];

    fused_mean_lstm_kernel<<<8192 + NLSTMBLK, 256>>>(
        x,
        (const float*)d_in[1],  (const float*)d_in[2],
        (const float*)d_in[3],  (const float*)d_in[4],
        (const float*)d_in[5],  (const float*)d_in[6],
        (const float*)d_in[7],  (const float*)d_in[8],
        (const float*)d_in[9],  (const float*)d_in[10],
        (const float*)d_in[11], (const float*)d_in[12],
        (const float*)d_in[13], (const float*)d_in[14],
        (const float*)d_in[15], (const float*)d_in[16],
        (const float*)d_in[17], (const float*)d_in[18]);

    scale_kernel<<<73728, 256>>>(x, (float*)d_out);
}

// round 12
// speedup vs baseline: 2.0997x; 2.0997x over previous
#include <cuda_runtime.h>

// Problem constants: x [2, 64, 64, 96, 96]; NSEQ = bs*c = 128; T = d = 64; HID = 4
#define NSEQ 128
#define TSTEPS 64
#define ROWVEC 2304          // 96*96/4
#define VECS_PER_BC 147456   // 64*96*96/4

__device__ float g_mean[NSEQ * TSTEPS];            // [seq=b*64+c][t=d]
__device__ __align__(16) float g_last[NSEQ * 8];   // [seq][fwd h(4) | bwd h(4)]
__device__ float g_scale[NSEQ];                    // sigmoid output per (b,c)
__device__ unsigned g_ctr;                         // last-block counter

__device__ __forceinline__ float tanh_ap(float x) {
    float y;
    asm("tanh.approx.f32 %0, %1;" : "=f"(y) : "f"(x));
    return y;
}
__device__ __forceinline__ float sig_ap(float x) {
    return fmaf(0.5f, tanh_ap(0.5f * x), 0.5f);
}
__device__ __forceinline__ float sig_acc(float x) {
    return __fdividef(1.f, 1.f + __expf(-x));
}

// ---------------------------------------------------------------------------
// Kernel 1: mean over H,W for each (b,c,d) row. One block per row.
// (Unchanged from R9 — measured 45.9us @ 84% DRAM.)
// ---------------------------------------------------------------------------
__global__ void mean_kernel(const float* __restrict__ x) {
    int r = blockIdx.x;
    const float4* p = reinterpret_cast<const float4*>(x) + (size_t)r * ROWVEC;
    float4 v[9];
#pragma unroll
    for (int i = 0; i < 9; ++i) v[i] = p[threadIdx.x + i * 256];
    float s = 0.f;
#pragma unroll
    for (int i = 0; i < 9; ++i) s += (v[i].x + v[i].y) + (v[i].z + v[i].w);
#pragma unroll
    for (int off = 16; off > 0; off >>= 1)
        s += __shfl_down_sync(0xffffffffu, s, off);
    __shared__ float red[8];
    int warp = threadIdx.x >> 5, lane = threadIdx.x & 31;
    if (lane == 0) red[warp] = s;
    __syncthreads();
    if (threadIdx.x < 8) {
        s = red[threadIdx.x];
        s += __shfl_down_sync(0xffu, s, 4);
        s += __shfl_down_sync(0xffu, s, 2);
        s += __shfl_down_sync(0xffu, s, 1);
        if (threadIdx.x == 0) g_mean[r] = s * (1.f / 9216.f);
    }
}

// ---------------------------------------------------------------------------
// Kernel 2: 2-layer biLSTM (hidden=4), 4 threads per cell, warp 0 only.
// 32 blocks x 128 threads; warps 1-3 idle until the fc epilogue.
// The last-arriving block runs the SE MLP with ALL 4 WARPS: each warp does
// a batched-8-row GEMV of w1 (8 independent load streams -> one DRAM latency
// round instead of 16 serialized ones).
// ---------------------------------------------------------------------------
__global__ void lstm_kernel(
    const float* __restrict__ wih0f, const float* __restrict__ whh0f,
    const float* __restrict__ bih0f, const float* __restrict__ bhh0f,
    const float* __restrict__ wih0b, const float* __restrict__ whh0b,
    const float* __restrict__ bih0b, const float* __restrict__ bhh0b,
    const float* __restrict__ wih1f, const float* __restrict__ whh1f,
    const float* __restrict__ bih1f, const float* __restrict__ bhh1f,
    const float* __restrict__ wih1b, const float* __restrict__ whh1b,
    const float* __restrict__ bih1b, const float* __restrict__ bhh1b,
    const float* __restrict__ w1,    const float* __restrict__ w2) {
    __shared__ float s_mean[256];                     // 4 seqs x 64 t
    __shared__ __align__(16) float s_h0[4][516];      // 4 x (64 t x 8) + pad
    __shared__ __align__(16) float z[1024];           // fc input [2 x 512]
    __shared__ float h1s[64];                         // fc hidden [2 x 32]
    __shared__ unsigned s_last;

    int tid = threadIdx.x;

    if (tid < 32) {
        int j   = tid & 3;        // cell index within hidden=4
        int u   = tid >> 2;       // unit 0..7
        int sl  = u >> 1;         // local seq 0..3
        int dir = u & 1;

        // ---- register-load weights ----
        const float* WIH0 = dir ? wih0b : wih0f;
        const float* WHH0 = dir ? whh0b : whh0f;
        const float* BI0  = dir ? bih0b : bih0f;
        const float* BH0  = dir ? bhh0b : bhh0f;
        float w_ih0[4], w_hh0[16], b0[4];
#pragma unroll
        for (int g = 0; g < 4; ++g) {
            int k = g * 4 + j;
            w_ih0[g] = WIH0[k];
            b0[g]    = BI0[k] + BH0[k];
#pragma unroll
            for (int m = 0; m < 4; ++m) w_hh0[g * 4 + m] = WHH0[k * 4 + m];
        }
        const float* WIH1 = (tid < 16) ? wih1f : wih1b;
        const float* WHH1 = (tid < 16) ? whh1f : whh1b;
        const float* BI1  = (tid < 16) ? bih1f : bih1b;
        const float* BH1  = (tid < 16) ? bhh1f : bhh1b;
        int j1 = tid & 3;
        float w1i[32], w1h[16], b1[4];
#pragma unroll
        for (int g = 0; g < 4; ++g) {
            int k = g * 4 + j1;
            b1[g] = BI1[k] + BH1[k];
#pragma unroll
            for (int m = 0; m < 8; ++m) w1i[g * 8 + m] = WIH1[k * 8 + m];
#pragma unroll
            for (int m = 0; m < 4; ++m) w1h[g * 4 + m] = WHH1[k * 4 + m];
        }

#pragma unroll
        for (int i = 0; i < 8; ++i)
            s_mean[tid + i * 32] = g_mean[blockIdx.x * 256 + tid + i * 32];
        __syncwarp();

        // ---------------- layer 0 ----------------
        {
            float hj = 0.f, cj = 0.f;
            const float* mrow = s_mean + sl * 64;
            float* hrow = s_h0[sl];
            int foff = dir * 4 + j;
            for (int st = 0; st < TSTEPS; ++st) {
                int t = dir ? (TSTEPS - 1 - st) : st;
                float xt = mrow[t];
                float h0 = __shfl_sync(0xffffffffu, hj, 0, 4);
                float h1 = __shfl_sync(0xffffffffu, hj, 1, 4);
                float h2 = __shfl_sync(0xffffffffu, hj, 2, 4);
                float h3 = __shfl_sync(0xffffffffu, hj, 3, 4);
                float ga[4];
#pragma unroll
                for (int g = 0; g < 4; ++g) {
                    float p0 = fmaf(w_ih0[g], xt, b0[g]);
                    p0 = fmaf(w_hh0[g * 4 + 0], h0, p0);
                    float p1 = fmaf(w_hh0[g * 4 + 2], h2, w_hh0[g * 4 + 1] * h1);
                    float p2 = w_hh0[g * 4 + 3] * h3;
                    ga[g] = p0 + (p1 + p2);
                }
                float ig = sig_ap(ga[0]), fg = sig_ap(ga[1]);
                float gg = tanh_ap(ga[2]), og = sig_ap(ga[3]);
                cj = fmaf(fg, cj, ig * gg);
                hj = og * tanh_ap(cj);
                hrow[t * 8 + foff] = hj;
            }
        }
        __syncwarp();

        // ---------------- layer 1 ----------------
        if (tid < 16) {
            int s1 = tid >> 2;
            const float* hrow = s_h0[s1];
            float hj = 0.f, cj = 0.f;
            for (int t = 0; t < TSTEPS; ++t) {
                float4 xa = *reinterpret_cast<const float4*>(hrow + t * 8);
                float4 xb = *reinterpret_cast<const float4*>(hrow + t * 8 + 4);
                float h0 = __shfl_sync(0x0000ffffu, hj, 0, 4);
                float h1 = __shfl_sync(0x0000ffffu, hj, 1, 4);
                float h2 = __shfl_sync(0x0000ffffu, hj, 2, 4);
                float h3 = __shfl_sync(0x0000ffffu, hj, 3, 4);
                float ga[4];
#pragma unroll
                for (int g = 0; g < 4; ++g) {
                    const float* wi = w1i + g * 8;
                    const float* wh = w1h + g * 4;
                    float p0 = fmaf(wi[0], xa.x, b1[g]);
                    p0 = fmaf(wi[1], xa.y, p0);
                    float p1 = fmaf(wi[3], xa.w, wi[2] * xa.z);
                    float p2 = fmaf(wi[5], xb.y, wi[4] * xb.x);
                    float p3 = fmaf(wi[7], xb.w, wi[6] * xb.z);
                    float p4 = fmaf(wh[1], h1, wh[0] * h0);
                    float p5 = fmaf(wh[3], h3, wh[2] * h2);
                    ga[g] = ((p0 + p1) + (p2 + p3)) + (p4 + p5);
                }
                float ig = sig_ap(ga[0]), fg = sig_ap(ga[1]);
                float gg = tanh_ap(ga[2]), og = sig_ap(ga[3]);
                cj = fmaf(fg, cj, ig * gg);
                hj = og * tanh_ap(cj);
            }
            g_last[(blockIdx.x * 4 + s1) * 8 + j1] = hj;
        } else {
            // backward: only the first processed step (original t=T-1) is used
            int s1 = (tid - 16) >> 2;
            const float* hrow = s_h0[s1];
            float4 xa = *reinterpret_cast<const float4*>(hrow + (TSTEPS - 1) * 8);
            float4 xb = *reinterpret_cast<const float4*>(hrow + (TSTEPS - 1) * 8 + 4);
            float ga[4];
#pragma unroll
            for (int g = 0; g < 4; ++g) {
                const float* wi = w1i + g * 8;
                float p0 = fmaf(wi[0], xa.x, b1[g]);
                p0 = fmaf(wi[1], xa.y, p0);
                float p1 = fmaf(wi[3], xa.w, wi[2] * xa.z);
                float p2 = fmaf(wi[5], xb.y, wi[4] * xb.x);
                float p3 = fmaf(wi[7], xb.w, wi[6] * xb.z);
                ga[g] = (p0 + p1) + (p2 + p3);
            }
            float cj = sig_ap(ga[0]) * tanh_ap(ga[2]);
            float hj = sig_ap(ga[3]) * tanh_ap(cj);
            g_last[(blockIdx.x * 4 + s1) * 8 + 4 + j1] = hj;
        }
    }

    // ---------------- fc (SE MLP), last-arriving block, ALL 4 warps ---------
    __syncthreads();
    if (tid == 0) {
        __threadfence();
        s_last = (atomicAdd(&g_ctr, 1u) == 31u) ? 1u : 0u;
    }
    __syncthreads();
    if (!s_last) return;
    __threadfence();  // acquire: other blocks' g_last stores

    // stage z (1024 floats) with 128 threads, float4 (g_last is 16B-aligned)
    {
        float4* z4 = reinterpret_cast<float4*>(z);
        const float4* gl4 = reinterpret_cast<const float4*>(g_last);
        z4[tid] = gl4[tid];
        z4[tid + 128] = gl4[tid + 128];
    }
    __syncthreads();

    // h1 = relu(z @ w1.T): warp w handles rows 8w..8w+7, batched — 8
    // independent coalesced load streams per k-chunk, z from SMEM.
    {
        int w = tid >> 5, lane = tid & 31;
        float acc0[8], acc1[8];
#pragma unroll
        for (int r = 0; r < 8; ++r) { acc0[r] = 0.f; acc1[r] = 0.f; }
        const float* wbase = w1 + (w * 8) * 512;
#pragma unroll
        for (int cch = 0; cch < 16; ++cch) {
            int k = cch * 32 + lane;
            float zz0 = z[k], zz1 = z[512 + k];
#pragma unroll
            for (int r = 0; r < 8; ++r) {
                float wv = wbase[r * 512 + k];
                acc0[r] = fmaf(wv, zz0, acc0[r]);
                acc1[r] = fmaf(wv, zz1, acc1[r]);
            }
        }
#pragma unroll
        for (int r = 0; r < 8; ++r) {
#pragma unroll
            for (int off = 16; off > 0; off >>= 1) {
                acc0[r] += __shfl_down_sync(0xffffffffu, acc0[r], off);
                acc1[r] += __shfl_down_sync(0xffffffffu, acc1[r], off);
            }
            if (lane == 0) {
                h1s[w * 8 + r]      = fmaxf(acc0[r], 0.f);
                h1s[32 + w * 8 + r] = fmaxf(acc1[r], 0.f);
            }
        }
    }
    __syncthreads();

    // scale = sigmoid(h1 @ w2.T): thread ch<64 does both batches; w2 rows are
    // thread-contiguous (128B each) -> L1 line reuse across the m-loop.
    if (tid < 64) {
        const float* wr = w2 + tid * 32;
        float a0 = 0.f, a1 = 0.f;
#pragma unroll
        for (int m = 0; m < 32; ++m) {
            float wv = wr[m];
            a0 = fmaf(wv, h1s[m], a0);
            a1 = fmaf(wv, h1s[32 + m], a1);
        }
        g_scale[tid]      = sig_acc(a0);
        g_scale[64 + tid] = sig_acc(a1);
    }
    if (tid == 0) g_ctr = 0;  // reset for next graph replay
}

// ---------------------------------------------------------------------------
// Kernel 3: out = x * scale[bc]. One float4 per thread, exact grid
// (the R3-measured configuration).
// ---------------------------------------------------------------------------
__global__ void scale_kernel(const float* __restrict__ x,
                             float* __restrict__ out) {
    unsigned v = blockIdx.x * 256u + threadIdx.x;  // < 18,874,368
    unsigned bc = v / VECS_PER_BC;                 // 0..127
    float sc = g_scale[bc];
    float4 t = reinterpret_cast<const float4*>(x)[v];
    t.x *= sc; t.y *= sc; t.z *= sc; t.w *= sc;
    __stcs(reinterpret_cast<float4*>(out) + v, t);
}

// ---------------------------------------------------------------------------
extern "C" void kernel_launch(void* const* d_in, const int* in_sizes, int n_in,
                              void* d_out, int out_size) {
    const float* x = (const float*)d_in[0];

    mean_kernel<<<8192, 256>>>(x);

    lstm_kernel<<<32, 128>>>(
        (const float*)d_in[1],  (const float*)d_in[2],
        (const float*)d_in[3],  (const float*)d_in[4],
        (const float*)d_in[5],  (const float*)d_in[6],
        (const float*)d_in[7],  (const float*)d_in[8],
        (const float*)d_in[9],  (const float*)d_in[10],
        (const float*)d_in[11], (const float*)d_in[12],
        (const float*)d_in[13], (const float*)d_in[14],
        (const float*)d_in[15], (const float*)d_in[16],
        (const float*)d_in[17], (const float*)d_in[18]);

    scale_kernel<<<73728, 256>>>(x, (float*)d_out);
}